// round 8
// baseline (speedup 1.0000x reference)
#include <cuda_runtime.h>

#define CAM_FL  540.0f
#define HALF_W  320.0f
#define HALF_H  240.0f
#define CAM_W   640
#define CAM_H   480
#define HW      (CAM_H * CAM_W)
#define PB      512      // particles per block
#define TPB     256      // threads per block
#define CAP     128      // smem survivor capacity (mean ~23/block; overflow -> slow path)

// per-batch camera: col j = (R[0][j], R[1][j], R[2][j], -t[j]) with t = pose·R
__device__ float4 g_cam[8][3];

__global__ void k_pre(const float* __restrict__ pose,
                      const float* __restrict__ rotq, int B) {
    const int b = threadIdx.x;
    if (b >= B) return;

    float qx = rotq[b * 4 + 0];
    float qy = rotq[b * 4 + 1];
    float qz = rotq[b * 4 + 2];
    float qw = rotq[b * 4 + 3];
    float inv = rsqrtf(qx * qx + qy * qy + qz * qz + qw * qw);
    qx = -qx * inv; qy = -qy * inv; qz = -qz * inv; qw = qw * inv;

    const float qx2 = qx * qx, qy2 = qy * qy, qz2 = qz * qz;
    const float qxqy = qx * qy, qxqz = qx * qz, qxqw = qx * qw;
    const float qyqz = qy * qz, qyqw = qy * qw, qzqw = qz * qw;
    const float r00 = 1.f - 2.f * qy2 - 2.f * qz2;
    const float r10 = 2.f * qxqy - 2.f * qzqw;
    const float r20 = 2.f * qxqz + 2.f * qyqw;
    const float r01 = 2.f * qxqy + 2.f * qzqw;
    const float r11 = 1.f - 2.f * qx2 - 2.f * qz2;
    const float r21 = 2.f * qyqz - 2.f * qxqw;
    const float r02 = 2.f * qxqz - 2.f * qyqw;
    const float r12 = 2.f * qyqz + 2.f * qxqw;
    const float r22 = 1.f - 2.f * qx2 - 2.f * qy2;

    const float cx = pose[b * 3 + 0];
    const float cy = pose[b * 3 + 1];
    const float cz = pose[b * 3 + 2];
    // t_j = pose · R[:,j]
    const float t0 = cx * r00 + cy * r10 + cz * r20;
    const float t1 = cx * r01 + cy * r11 + cz * r21;
    const float t2 = cx * r02 + cy * r12 + cz * r22;

    g_cam[b][0] = make_float4(r00, r10, r20, -t0);
    g_cam[b][1] = make_float4(r01, r11, r21, -t1);
    g_cam[b][2] = make_float4(r02, r12, r22, -t2);
}

__global__ __launch_bounds__(TPB, 6) void proj_kernel(
    const float* __restrict__ locs,
    const float* __restrict__ depth,
    float* __restrict__ out,
    int N)
{
    // record (16 floats): [0..7]=wx8 (aligned 8-slot x weights, pre-masked)
    // [8]=z  [9]=packed(bx | (ib+4)<<10)  [10..14]=wy[0..4]  [15]=pad
    __shared__ float s_rec[CAP][16];
    __shared__ int   s_cnt;

    const int tid = threadIdx.x;
    const int b   = blockIdx.y;

    if (tid == 0) s_cnt = 0;

    const float4 c0 = __ldg(&g_cam[b][0]);
    const float4 c1 = __ldg(&g_cam[b][1]);
    const float4 c2 = __ldg(&g_cam[b][2]);

    const float* dimg = depth + b * HW;
    float*       oimg = out   + b * HW;

    __syncthreads();   // s_cnt init visible

    // ---------------- Phase 1: project 2 paired particles/thread, compact ----------------
    const float C1 = 0.60653066f;   // exp(-0.5)
    const float C2 = 0.13533528f;   // exp(-2)

    const int  gpart = blockIdx.x * PB;
    const float* lpB = locs + ((long long)b * N + gpart) * 3;
    const int  i0 = 2 * tid;

    float X[2], Y[2], Z[2];
    bool have[2];
    if (gpart + PB <= N) {           // full block (uniform fast path)
        const float2 A  = *(const float2*)(lpB + i0 * 3);
        const float2 Bv = *(const float2*)(lpB + i0 * 3 + 2);
        const float2 Cv = *(const float2*)(lpB + i0 * 3 + 4);
        X[0] = A.x;  Y[0] = A.y;  Z[0] = Bv.x;
        X[1] = Bv.y; Y[1] = Cv.x; Z[1] = Cv.y;
        have[0] = have[1] = true;
    } else {
        have[0] = (gpart + i0) < N;
        have[1] = (gpart + i0 + 1) < N;
        X[0] = Y[0] = Z[0] = X[1] = Y[1] = Z[1] = 0.f;
        if (have[0]) { X[0] = lpB[i0*3];   Y[0] = lpB[i0*3+1]; Z[0] = lpB[i0*3+2]; }
        if (have[1]) { X[1] = lpB[i0*3+3]; Y[1] = lpB[i0*3+4]; Z[1] = lpB[i0*3+5]; }
    }

#pragma unroll
    for (int j = 0; j < 2; j++) {
        const float z = fmaf(X[j], c2.x, fmaf(Y[j], c2.y, fmaf(Z[j], c2.z, c2.w)));

        bool ok = false;
        float px = 0.f, py = 0.f;
        if (have[j] && z > 0.f) {
            const float x = fmaf(X[j], c0.x, fmaf(Y[j], c0.y, fmaf(Z[j], c0.z, c0.w)));
            const float y = fmaf(X[j], c1.x, fmaf(Y[j], c1.y, fmaf(Z[j], c1.z, c1.w)));
            const float invz = __frcp_rn(z);
            px = x * invz * CAM_FL + HALF_W;
            py = y * invz * CAM_FL + HALF_H;
            ok = (px >= -2.f && px < 642.f && py >= -2.f && py < 482.f);
        }

        const unsigned m = __ballot_sync(0xffffffffu, ok);
        int idx = 0;
        if (m) {
            const int lane = tid & 31;
            const int lead = __ffs(m) - 1;
            int wbase = 0;
            if (lane == lead) wbase = atomicAdd(&s_cnt, __popc(m));
            wbase = __shfl_sync(0xffffffffu, wbase, lead);
            idx = wbase + __popc(m & ((1u << lane) - 1u));
        }

        if (ok) {
            const float fx = floorf(px), fy = floorf(py);
            const int jb = (int)fx - 2;
            const int ib = (int)fy - 2;                 // in [-4, 479]
            const float u = fx - px;
            const float v = fy - py;

            const float ax  = __expf(-0.5f * u * u);
            const float ex  = __expf(-u);
            const float exi = __frcp_rn(ex);
            const float wx0 = ax * exi * exi * C2;
            const float wx1 = ax * exi * C1;
            const float wx2 = ax;
            const float wx3 = ax * ex * C1;
            const float wx4 = ax * ex * ex * C2;

            const float ay  = __expf(-0.5f * v * v);
            const float ey  = __expf(-v);
            const float eyi = __frcp_rn(ey);
            const float wy0 = ay * eyi * eyi * C2;
            const float wy1 = ay * eyi * C1;
            const float wy2 = ay;
            const float wy3 = ay * ey * C1;
            const float wy4 = ay * ey * ey * C2;

            if (idx < CAP) {
                const int bx = min(max(jb, 0) & ~3, 632);   // aligned 8-slot window
                const int off = jb - bx;                    // in [-2, 7]

                float* r = s_rec[idx];
                *(float4*)(r)     = make_float4(0.f, 0.f, 0.f, 0.f);
                *(float4*)(r + 4) = make_float4(0.f, 0.f, 0.f, 0.f);
                int s;
                s = off + 0; if (s >= 0 && s <= 7) r[s] = wx0;
                s = off + 1; if (s >= 0 && s <= 7) r[s] = wx1;
                s = off + 2; if (s >= 0 && s <= 7) r[s] = wx2;
                s = off + 3; if (s >= 0 && s <= 7) r[s] = wx3;
                s = off + 4; if (s >= 0 && s <= 7) r[s] = wx4;
                r[8]  = z;
                r[9]  = __int_as_float(bx | ((ib + 4) << 10));
                r[10] = wy0; r[11] = wy1; r[12] = wy2; r[13] = wy3; r[14] = wy4;
            } else {
                // overflow slow path (statistically unreachable): direct splat
                const float wxv[5] = {wx0, wx1, wx2, wx3, wx4};
                const float wyv[5] = {wy0, wy1, wy2, wy3, wy4};
                for (int ii = 0; ii < 5; ii++) {
                    const int yy = ib + ii;
                    if (yy < 0 || yy >= CAM_H) continue;
                    for (int jj = 0; jj < 5; jj++) {
                        const int xx = jb + jj;
                        if (xx < 0 || xx >= CAM_W) continue;
                        const float d = __ldg(dimg + yy * CAM_W + xx);
                        if (z <= d) atomicAdd(oimg + yy * CAM_W + xx, wyv[ii] * wxv[jj]);
                    }
                }
            }
        }
    }

    __syncthreads();

    // ---------------- Phase 2: warp-coalesced splat ----------------
    // 8 consecutive lanes own the 8 aligned slots of one survivor; a warp
    // processes 4 survivors. Depth loads and reds hit 4 contiguous 32B
    // segments per warp-op (coalesced), 5 rows loaded up-front (MLP=5).
    const int cnt  = min(s_cnt, CAP);
    const int wid  = tid >> 5;
    const int lane = tid & 31;
    const int sub  = lane >> 3;     // 0..3: survivor within warp-task
    const int slot = lane & 7;      // 0..7: x-slot

    for (int s0 = wid * 4; s0 < cnt; s0 += (TPB / 32) * 4) {
        const int s = s0 + sub;
        if (s >= cnt) continue;

        const float* r = s_rec[s];
        const float wx = r[slot];
        const float z  = r[8];
        const int   pk = __float_as_int(r[9]);
        const int   bx = pk & 0x3ff;
        const int   ib = ((pk >> 10) & 0x1ff) - 4;

        const int base = ib * CAM_W + bx + slot;

        float dd[5];
        int   oo[5];
        bool  rk[5];
#pragma unroll
        for (int row = 0; row < 5; row++) {
            const int yy = ib + row;
            rk[row] = (yy >= 0) && (yy < CAM_H) && (wx != 0.f);
            oo[row] = base + row * CAM_W;
            dd[row] = rk[row] ? __ldg(dimg + oo[row]) : -1.f;
        }
#pragma unroll
        for (int row = 0; row < 5; row++) {
            if (rk[row] && z <= dd[row]) {
                atomicAdd(oimg + oo[row], r[10 + row] * wx);
            }
        }
    }
}

extern "C" void kernel_launch(void* const* d_in, const int* in_sizes, int n_in,
                              void* d_out, int out_size) {
    const float* locs  = (const float*)d_in[0];
    const float* pose  = (const float*)d_in[1];
    const float* rotq  = (const float*)d_in[2];
    const float* depth = (const float*)d_in[3];
    float* out = (float*)d_out;

    const int B = in_sizes[1] / 3;           // 4
    const int N = in_sizes[0] / (3 * B);     // 200000

    cudaMemsetAsync(d_out, 0, (size_t)out_size * sizeof(float), 0);
    k_pre<<<1, 32>>>(pose, rotq, B);

    dim3 grid((N + PB - 1) / PB, B);
    proj_kernel<<<grid, TPB>>>(locs, depth, out, N);
}

// round 9
// speedup vs baseline: 1.1555x; 1.1555x over previous
#include <cuda_runtime.h>

#define CAM_FL  540.0f
#define HALF_W  320.0f
#define HALF_H  240.0f
#define CAM_W   640
#define CAM_H   480
#define HW      (CAM_H * CAM_W)
#define PB      512      // particles per block
#define TPB     256      // threads per block
#define CAP     128      // smem survivor capacity (mean ~23/block; overflow -> slow path)

__global__ __launch_bounds__(TPB, 6) void proj_kernel(
    const float* __restrict__ locs,
    const float* __restrict__ pose,
    const float* __restrict__ rotq,
    const float* __restrict__ depth,
    float* __restrict__ out,
    int N)
{
    // record (16 floats): [0..7]=wx8 (aligned 8-slot x weights, pre-masked)
    // [8]=z  [9]=packed(bx | (ib+4)<<10)  [10..14]=wy[0..4]  [15]=pad
    __shared__ float s_rec[CAP][16];
    __shared__ float s_px[CAP];
    __shared__ float s_py[CAP];
    __shared__ float s_pz[CAP];
    __shared__ int   s_cnt;

    const int tid = threadIdx.x;
    const int b   = blockIdx.y;

    if (tid == 0) s_cnt = 0;

    // --- quaternion (normalized, conjugated) -> rotation matrix ---
    // (uniform per-thread recompute: overlaps the locs load latency, ~free)
    float qx = __ldg(rotq + b * 4 + 0);
    float qy = __ldg(rotq + b * 4 + 1);
    float qz = __ldg(rotq + b * 4 + 2);
    float qw = __ldg(rotq + b * 4 + 3);
    float inv = rsqrtf(qx * qx + qy * qy + qz * qz + qw * qw);
    qx = -qx * inv; qy = -qy * inv; qz = -qz * inv; qw = qw * inv;

    const float qx2 = qx * qx, qy2 = qy * qy, qz2 = qz * qz;
    const float qxqy = qx * qy, qxqz = qx * qz, qxqw = qx * qw;
    const float qyqz = qy * qz, qyqw = qy * qw, qzqw = qz * qw;
    const float r00 = 1.f - 2.f * qy2 - 2.f * qz2;
    const float r10 = 2.f * qxqy - 2.f * qzqw;
    const float r20 = 2.f * qxqz + 2.f * qyqw;
    const float r01 = 2.f * qxqy + 2.f * qzqw;
    const float r11 = 1.f - 2.f * qx2 - 2.f * qz2;
    const float r21 = 2.f * qyqz - 2.f * qxqw;
    const float r02 = 2.f * qxqz - 2.f * qyqw;
    const float r12 = 2.f * qyqz + 2.f * qxqw;
    const float r22 = 1.f - 2.f * qx2 - 2.f * qy2;

    const float cx = __ldg(pose + b * 3 + 0);
    const float cy = __ldg(pose + b * 3 + 1);
    const float cz = __ldg(pose + b * 3 + 2);

    const float* dimg = depth + b * HW;
    float*       oimg = out   + b * HW;

    __syncthreads();   // s_cnt init visible

    // ---------------- Phase 1: project 2 paired particles/thread, compact (px,py,z) ----------------
    const int  gpart = blockIdx.x * PB;
    const float* lpB = locs + ((long long)b * N + gpart) * 3;
    const int  i0 = 2 * tid;

    float X[2], Y[2], Z[2];
    bool have[2];
    if (gpart + PB <= N) {           // full block (uniform fast path)
        const float2 A  = *(const float2*)(lpB + i0 * 3);
        const float2 Bv = *(const float2*)(lpB + i0 * 3 + 2);
        const float2 Cv = *(const float2*)(lpB + i0 * 3 + 4);
        X[0] = A.x;  Y[0] = A.y;  Z[0] = Bv.x;
        X[1] = Bv.y; Y[1] = Cv.x; Z[1] = Cv.y;
        have[0] = have[1] = true;
    } else {
        have[0] = (gpart + i0) < N;
        have[1] = (gpart + i0 + 1) < N;
        X[0] = Y[0] = Z[0] = X[1] = Y[1] = Z[1] = 0.f;
        if (have[0]) { X[0] = lpB[i0*3];   Y[0] = lpB[i0*3+1]; Z[0] = lpB[i0*3+2]; }
        if (have[1]) { X[1] = lpB[i0*3+3]; Y[1] = lpB[i0*3+4]; Z[1] = lpB[i0*3+5]; }
    }

#pragma unroll
    for (int j = 0; j < 2; j++) {
        const float p0 = X[j] - cx, p1 = Y[j] - cy, p2 = Z[j] - cz;
        const float z = p0 * r02 + p1 * r12 + p2 * r22;

        bool ok = false;
        float px = 0.f, py = 0.f;
        if (have[j] && z > 0.f) {
            const float x = p0 * r00 + p1 * r10 + p2 * r20;
            const float y = p0 * r01 + p1 * r11 + p2 * r21;
            const float invz = __frcp_rn(z);
            px = x * invz * CAM_FL + HALF_W;
            py = y * invz * CAM_FL + HALF_H;
            ok = (px >= -2.f && px < 642.f && py >= -2.f && py < 482.f);
        }

        const unsigned m = __ballot_sync(0xffffffffu, ok);
        int idx = 0;
        if (m) {
            const int lane = tid & 31;
            const int lead = __ffs(m) - 1;
            int wbase = 0;
            if (lane == lead) wbase = atomicAdd(&s_cnt, __popc(m));
            wbase = __shfl_sync(0xffffffffu, wbase, lead);
            idx = wbase + __popc(m & ((1u << lane) - 1u));
        }

        if (ok) {
            if (idx < CAP) {
                s_px[idx] = px;
                s_py[idx] = py;
                s_pz[idx] = z;
            } else {
                // overflow slow path (statistically unreachable): direct splat
                const float C1 = 0.60653066f, C2 = 0.13533528f;
                const float fx = floorf(px), fy = floorf(py);
                const int jb = (int)fx - 2, ib = (int)fy - 2;
                const float u = fx - px, v = fy - py;
                const float ax = __expf(-0.5f * u * u);
                const float ex = __expf(-u);
                const float exi = __frcp_rn(ex);
                const float wxv[5] = {ax*exi*exi*C2, ax*exi*C1, ax, ax*ex*C1, ax*ex*ex*C2};
                const float ay = __expf(-0.5f * v * v);
                const float ey = __expf(-v);
                const float eyi = __frcp_rn(ey);
                const float wyv[5] = {ay*eyi*eyi*C2, ay*eyi*C1, ay, ay*ey*C1, ay*ey*ey*C2};
                for (int ii = 0; ii < 5; ii++) {
                    const int yy = ib + ii;
                    if (yy < 0 || yy >= CAM_H) continue;
                    for (int jj = 0; jj < 5; jj++) {
                        const int xx = jb + jj;
                        if (xx < 0 || xx >= CAM_W) continue;
                        const float d = __ldg(dimg + yy * CAM_W + xx);
                        if (z <= d) atomicAdd(oimg + yy * CAM_W + xx, wyv[ii] * wxv[jj]);
                    }
                }
            }
        }
    }

    __syncthreads();

    // ---------------- Phase 1.5: dense weight/record computation ----------------
    const int cnt = min(s_cnt, CAP);
    {
        const float C1 = 0.60653066f;   // exp(-0.5)
        const float C2 = 0.13533528f;   // exp(-2)
        for (int t = tid; t < cnt; t += TPB) {
            const float px = s_px[t];
            const float py = s_py[t];
            const float z  = s_pz[t];

            const float fx = floorf(px), fy = floorf(py);
            const int jb = (int)fx - 2;
            const int ib = (int)fy - 2;                 // in [-4, 479]
            const int bx = min(max(jb, 0) & ~3, 632);   // aligned 8-slot window
            const int off = jb - bx;                    // in [-2, 7]
            const float u = fx - px;
            const float v = fy - py;

            const float ax  = __expf(-0.5f * u * u);
            const float ex  = __expf(-u);
            const float exi = __frcp_rn(ex);

            float* r = s_rec[t];
            *(float4*)(r)     = make_float4(0.f, 0.f, 0.f, 0.f);
            *(float4*)(r + 4) = make_float4(0.f, 0.f, 0.f, 0.f);
            int s;
            s = off + 0; if (s >= 0 && s <= 7) r[s] = ax * exi * exi * C2;
            s = off + 1; if (s >= 0 && s <= 7) r[s] = ax * exi * C1;
            s = off + 2; if (s >= 0 && s <= 7) r[s] = ax;
            s = off + 3; if (s >= 0 && s <= 7) r[s] = ax * ex * C1;
            s = off + 4; if (s >= 0 && s <= 7) r[s] = ax * ex * ex * C2;

            const float ay  = __expf(-0.5f * v * v);
            const float ey  = __expf(-v);
            const float eyi = __frcp_rn(ey);
            r[8]  = z;
            r[9]  = __int_as_float(bx | ((ib + 4) << 10));
            r[10] = ay * eyi * eyi * C2;
            r[11] = ay * eyi * C1;
            r[12] = ay;
            r[13] = ay * ey * C1;
            r[14] = ay * ey * ey * C2;
        }
    }

    __syncthreads();

    // ---------------- Phase 2: warp-coalesced splat ----------------
    // 8 consecutive lanes own the 8 aligned slots of one survivor; a warp
    // processes 4 survivors. Depth loads and reds hit 4 contiguous 32B
    // segments per warp-op (coalesced), 5 rows loaded up-front (MLP=5).
    const int wid  = tid >> 5;
    const int lane = tid & 31;
    const int sub  = lane >> 3;     // 0..3: survivor within warp-task
    const int slot = lane & 7;      // 0..7: x-slot

    for (int s0 = wid * 4; s0 < cnt; s0 += (TPB / 32) * 4) {
        const int s = s0 + sub;
        if (s >= cnt) continue;

        const float* r = s_rec[s];
        const float wx = r[slot];
        const float z  = r[8];
        const int   pk = __float_as_int(r[9]);
        const int   bx = pk & 0x3ff;
        const int   ib = ((pk >> 10) & 0x1ff) - 4;

        const int base = ib * CAM_W + bx + slot;

        float dd[5];
        int   oo[5];
        bool  rk[5];
#pragma unroll
        for (int row = 0; row < 5; row++) {
            const int yy = ib + row;
            rk[row] = (yy >= 0) && (yy < CAM_H) && (wx != 0.f);
            oo[row] = base + row * CAM_W;
            dd[row] = rk[row] ? __ldg(dimg + oo[row]) : -1.f;
        }
#pragma unroll
        for (int row = 0; row < 5; row++) {
            if (rk[row] && z <= dd[row]) {
                atomicAdd(oimg + oo[row], r[10 + row] * wx);
            }
        }
    }
}

extern "C" void kernel_launch(void* const* d_in, const int* in_sizes, int n_in,
                              void* d_out, int out_size) {
    const float* locs  = (const float*)d_in[0];
    const float* pose  = (const float*)d_in[1];
    const float* rotq  = (const float*)d_in[2];
    const float* depth = (const float*)d_in[3];
    float* out = (float*)d_out;

    const int B = in_sizes[1] / 3;           // 4
    const int N = in_sizes[0] / (3 * B);     // 200000

    cudaMemsetAsync(d_out, 0, (size_t)out_size * sizeof(float), 0);

    dim3 grid((N + PB - 1) / PB, B);
    proj_kernel<<<grid, TPB>>>(locs, pose, rotq, depth, out, N);
}